// round 1
// baseline (speedup 1.0000x reference)
#include <cuda_runtime.h>
#include <cstdint>

// Problem shape (fixed by setup_inputs)
constexpr int Bsz = 8, Np = 8192, Sp = 2048;
constexpr int C1 = 128, C2 = 256, CIN = 384, H1 = 256, H2 = 128;
constexpr int M = Bsz * Np; // 65536 points total

// ---------------- scratch (__device__ globals: no allocations allowed) ------
__device__ __align__(16) float g_x  [(size_t)M * CIN];  // concat [interp | f1]
__device__ __align__(16) float g_y1 [(size_t)M * H1];   // pre-BN layer-1 output
__device__             int   g_idx [M * 3];
__device__             float g_wt  [M * 3];
__device__ __align__(16) float g_w1t[CIN * H1];         // W1^T  [K x N]
__device__ __align__(16) float g_w2t[H1 * H2];          // W2^T
__device__ __align__(16) float g_psum[256 * 256];
__device__ __align__(16) float g_psq [256 * 256];
__device__ __align__(16) float g_scale1[H1], g_shift1[H1];
__device__ __align__(16) float g_scale2[H2], g_shift2[H2];

// ---------------- 3-NN per query point --------------------------------------
// grid = B*32 blocks of 256 threads; one query point per thread; xyz2 of the
// batch lives in smem as float4 (x,y,z,|p|^2).
__global__ void knn_kernel(const float* __restrict__ xyz1,
                           const float* __restrict__ xyz2) {
    __shared__ float4 sp[Sp];
    const int b = blockIdx.x >> 5;
    const int n = ((blockIdx.x & 31) << 8) + threadIdx.x;
    const float* x2 = xyz2 + (size_t)b * Sp * 3;
    for (int s = threadIdx.x; s < Sp; s += 256) {
        float px = x2[3 * s], py = x2[3 * s + 1], pz = x2[3 * s + 2];
        sp[s] = make_float4(px, py, pz, px * px + py * py + pz * pz);
    }
    __syncthreads();

    const float* q = xyz1 + ((size_t)b * Np + n) * 3;
    const float qx = q[0], qy = q[1], qz = q[2];
    const float q2 = qx * qx + qy * qy + qz * qz;

    float e0 = 3.4e38f, e1 = 3.4e38f, e2v = 3.4e38f;
    int i0 = 0, i1 = 0, i2 = 0;
#pragma unroll 4
    for (int s = 0; s < Sp; s++) {
        float4 p = sp[s];
        float dot = fmaf(qx, p.x, fmaf(qy, p.y, qz * p.z));
        float d2 = (q2 + p.w) - 2.0f * dot;     // same formula as reference
        if (d2 < e2v) {                          // strict <  => stable ties
            if (d2 < e1) {
                e2v = e1; i2 = i1;
                if (d2 < e0) { e1 = e0; i1 = i0; e0 = d2; i0 = s; }
                else         { e1 = d2; i1 = s; }
            } else { e2v = d2; i2 = s; }
        }
    }
    float d0 = sqrtf(fmaxf(e0,  0.f)) + 1e-10f;
    float d1 = sqrtf(fmaxf(e1,  0.f)) + 1e-10f;
    float d2 = sqrtf(fmaxf(e2v, 0.f)) + 1e-10f;
    float w0 = 1.f / d0, w1 = 1.f / d1, w2 = 1.f / d2;
    float inv = 1.f / (w0 + w1 + w2);
    const int m = b * Np + n;
    g_idx[3 * m] = i0; g_idx[3 * m + 1] = i1; g_idx[3 * m + 2] = i2;
    g_wt [3 * m] = w0 * inv; g_wt[3 * m + 1] = w1 * inv; g_wt[3 * m + 2] = w2 * inv;
}

// ---------------- interpolate + concat => x [M x 384] -----------------------
// one block (128 threads) per point; coalesced reads of the 3 neighbor rows.
__global__ void build_x_kernel(const float* __restrict__ f1,
                               const float* __restrict__ f2) {
    const int m = blockIdx.x;
    const int b = m >> 13;
    const int t = threadIdx.x;
    const int i0 = g_idx[3 * m], i1 = g_idx[3 * m + 1], i2 = g_idx[3 * m + 2];
    const float w0 = g_wt[3 * m], w1 = g_wt[3 * m + 1], w2 = g_wt[3 * m + 2];
    const float* r0 = f2 + ((size_t)b * Sp + i0) * C2;
    const float* r1 = f2 + ((size_t)b * Sp + i1) * C2;
    const float* r2 = f2 + ((size_t)b * Sp + i2) * C2;
    float* xr = g_x + (size_t)m * CIN;
    xr[t]        = w0 * r0[t]        + w1 * r1[t]        + w2 * r2[t];
    xr[t + 128]  = w0 * r0[t + 128]  + w1 * r1[t + 128]  + w2 * r2[t + 128];
    xr[C2 + t]   = f1[(size_t)m * C1 + t];
}

// ---------------- weight transpose (tiny, once per launch) ------------------
__global__ void transpose_kernel(const float* __restrict__ W,
                                 float* __restrict__ Wt, int O, int K) {
    int i = blockIdx.x * 256 + threadIdx.x;
    if (i < O * K) { int o = i / K, k = i - o * K; Wt[k * O + o] = W[i]; }
}

// ---------------- SGEMM: C[MxN] = A[MxK] * B[KxN] (B = W^T row-major) -------
// 128x128 tile, BK=8, 256 threads, 8x8 per thread.
// XFORM: apply per-channel BN+ReLU (scale/shift indexed by k) to A on load.
template <bool XFORM>
__global__ void __launch_bounds__(256, 2)
sgemm_kernel(const float* __restrict__ A, const float* __restrict__ Bm,
             float* __restrict__ C, int Kr, int Nr,
             const float* __restrict__ scale, const float* __restrict__ shift) {
    __shared__ float As[8][128];
    __shared__ float Bs[8][128];
    const int tid  = threadIdx.x;
    const int brow = blockIdx.x << 7;
    const int bcol = blockIdx.y << 7;
    const int ar = tid >> 1, ak = (tid & 1) << 2;      // A load: row, k-quad
    const int bk = tid >> 5, bc = (tid & 31) << 2;     // B load: k,  col-quad
    const int ty = tid >> 4, tx = tid & 15;

    const float* Ag = A  + (size_t)(brow + ar) * Kr + ak;
    const float* Bg = Bm + (size_t)bk * Nr + bcol + bc;

    float acc[8][8];
#pragma unroll
    for (int i = 0; i < 8; i++)
#pragma unroll
        for (int j = 0; j < 8; j++) acc[i][j] = 0.f;

    for (int kt = 0; kt < Kr; kt += 8) {
        float4 av = *(const float4*)(Ag + kt);
        if (XFORM) {
            float4 sc = *(const float4*)(scale + kt + ak);
            float4 sh = *(const float4*)(shift + kt + ak);
            av.x = fmaxf(fmaf(av.x, sc.x, sh.x), 0.f);
            av.y = fmaxf(fmaf(av.y, sc.y, sh.y), 0.f);
            av.z = fmaxf(fmaf(av.z, sc.z, sh.z), 0.f);
            av.w = fmaxf(fmaf(av.w, sc.w, sh.w), 0.f);
        }
        float4 bv = *(const float4*)(Bg + (size_t)kt * Nr);
        As[ak + 0][ar] = av.x; As[ak + 1][ar] = av.y;
        As[ak + 2][ar] = av.z; As[ak + 3][ar] = av.w;
        *(float4*)&Bs[bk][bc] = bv;
        __syncthreads();
#pragma unroll
        for (int k = 0; k < 8; k++) {
            float a[8], bb[8];
            *(float4*)&a[0]  = *(const float4*)&As[k][ty << 3];
            *(float4*)&a[4]  = *(const float4*)&As[k][(ty << 3) + 4];
            *(float4*)&bb[0] = *(const float4*)&Bs[k][tx << 3];
            *(float4*)&bb[4] = *(const float4*)&Bs[k][(tx << 3) + 4];
#pragma unroll
            for (int i = 0; i < 8; i++)
#pragma unroll
                for (int j = 0; j < 8; j++)
                    acc[i][j] = fmaf(a[i], bb[j], acc[i][j]);
        }
        __syncthreads();
    }
#pragma unroll
    for (int i = 0; i < 8; i++) {
        float* Cp = C + (size_t)(brow + (ty << 3) + i) * Nr + bcol + (tx << 3);
        *(float4*)Cp       = make_float4(acc[i][0], acc[i][1], acc[i][2], acc[i][3]);
        *(float4*)(Cp + 4) = make_float4(acc[i][4], acc[i][5], acc[i][6], acc[i][7]);
    }
}

// ---------------- BN stats: deterministic two-level reduction ----------------
template <int C>
__global__ void stats_partial_kernel(const float* __restrict__ Y) {
    const int c = threadIdx.x;            // blockDim = C
    constexpr int RPB = M / 256;          // 256 rows per block, grid = 256
    size_t base = (size_t)blockIdx.x * RPB * C + c;
    float s = 0.f, s2 = 0.f;
    for (int r = 0; r < RPB; r++) {
        float v = Y[base + (size_t)r * C];
        s += v; s2 = fmaf(v, v, s2);
    }
    g_psum[blockIdx.x * C + c] = s;
    g_psq [blockIdx.x * C + c] = s2;
}

template <int C>
__global__ void stats_final_kernel(const float* __restrict__ g,
                                   const float* __restrict__ be,
                                   float* __restrict__ scale,
                                   float* __restrict__ shift) {
    const int c = threadIdx.x;
    float s = 0.f, s2 = 0.f;
    for (int r = 0; r < 256; r++) { s += g_psum[r * C + c]; s2 += g_psq[r * C + c]; }
    const float invM = 1.0f / (float)M;
    float mean = s * invM;
    float var  = fmaf(s2, invM, -mean * mean);        // biased var (torch-style)
    float sc   = g[c] * rsqrtf(var + 1e-5f);
    scale[c] = sc;
    shift[c] = fmaf(-mean, sc, be[c]);                // conv bias cancels in BN
}

// ---------------- final BN+ReLU in place on d_out ---------------------------
__global__ void bnrelu_out_kernel(float* __restrict__ out) {
    int i = blockIdx.x * blockDim.x + threadIdx.x;    // float4 index
    float4 v = ((float4*)out)[i];
    int c = (i << 2) & (H2 - 1);
    v.x = fmaxf(fmaf(v.x, g_scale2[c],     g_shift2[c]),     0.f);
    v.y = fmaxf(fmaf(v.y, g_scale2[c + 1], g_shift2[c + 1]), 0.f);
    v.z = fmaxf(fmaf(v.z, g_scale2[c + 2], g_shift2[c + 2]), 0.f);
    v.w = fmaxf(fmaf(v.w, g_scale2[c + 3], g_shift2[c + 3]), 0.f);
    ((float4*)out)[i] = v;
}

// ---------------- launch -----------------------------------------------------
extern "C" void kernel_launch(void* const* d_in, const int* in_sizes, int n_in,
                              void* d_out, int out_size) {
    const float* xyz1 = (const float*)d_in[0];
    const float* xyz2 = (const float*)d_in[1];
    const float* f1   = (const float*)d_in[2];
    const float* f2   = (const float*)d_in[3];
    const float* W1   = (const float*)d_in[4];
    // b1 = d_in[5], b2 = d_in[9]: conv bias cancels exactly in training-mode BN
    const float* g1   = (const float*)d_in[6];
    const float* be1  = (const float*)d_in[7];
    const float* W2   = (const float*)d_in[8];
    const float* g2   = (const float*)d_in[10];
    const float* be2  = (const float*)d_in[11];
    float* out = (float*)d_out;

    float *px, *py1, *pw1t, *pw2t, *ps1, *pt1, *ps2, *pt2;
    cudaGetSymbolAddress((void**)&px,   g_x);
    cudaGetSymbolAddress((void**)&py1,  g_y1);
    cudaGetSymbolAddress((void**)&pw1t, g_w1t);
    cudaGetSymbolAddress((void**)&pw2t, g_w2t);
    cudaGetSymbolAddress((void**)&ps1,  g_scale1);
    cudaGetSymbolAddress((void**)&pt1,  g_shift1);
    cudaGetSymbolAddress((void**)&ps2,  g_scale2);
    cudaGetSymbolAddress((void**)&pt2,  g_shift2);

    transpose_kernel<<<(H1 * CIN + 255) / 256, 256>>>(W1, pw1t, H1, CIN);
    transpose_kernel<<<(H2 * H1  + 255) / 256, 256>>>(W2, pw2t, H2, H1);

    knn_kernel<<<Bsz * 32, 256>>>(xyz1, xyz2);
    build_x_kernel<<<M, 128>>>(f1, f2);

    // layer 1: y1 = x @ W1^T  (bias dropped; cancels in BN)
    sgemm_kernel<false><<<dim3(M / 128, H1 / 128), 256>>>(
        px, pw1t, py1, CIN, H1, nullptr, nullptr);
    stats_partial_kernel<H1><<<256, H1>>>(py1);
    stats_final_kernel<H1><<<1, H1>>>(g1, be1, ps1, pt1);

    // layer 2: y2 = relu(BN1(y1)) @ W2^T, BN1+ReLU fused into A load
    sgemm_kernel<true><<<dim3(M / 128, H2 / 128), 256>>>(
        py1, pw2t, out, H1, H2, ps1, pt1);
    stats_partial_kernel<H2><<<256, H2>>>(out);
    stats_final_kernel<H2><<<1, H2>>>(g2, be2, ps2, pt2);

    bnrelu_out_kernel<<<(M * H2 / 4) / 256, 256>>>(out);
}

// round 3
// speedup vs baseline: 1.9614x; 1.9614x over previous
#include <cuda_runtime.h>
#include <cstdint>

// Problem shape (fixed by setup_inputs)
constexpr int Bsz = 8, Np = 8192, Sp = 2048;
constexpr int C1 = 128, C2 = 256, CIN = 384, H1 = 256, H2 = 128;
constexpr int M = Bsz * Np; // 65536 points

// ---------------- scratch (__device__ globals) -------------------------------
__device__ __align__(16) float g_x  [(size_t)M * CIN];  // tf32-rounded concat
__device__ __align__(16) float g_y1 [(size_t)M * H1];   // pre-BN y1, then BN'd
__device__             int   g_idx [M * 3];
__device__             float g_wt  [M * 3];
__device__ __align__(16) float g_w1r[H1 * CIN];         // tf32-rounded W1
__device__ __align__(16) float g_w2r[H2 * H1];          // tf32-rounded W2
__device__ __align__(16) float g_psum[256 * 256];
__device__ __align__(16) float g_psq [256 * 256];
__device__ __align__(16) float g_scale1[H1], g_shift1[H1];
__device__ __align__(16) float g_scale2[H2], g_shift2[H2];

// ---------------- PTX helpers (sm_80+ only; no 'a'-suffix features) ----------
__device__ __forceinline__ uint32_t smem_u32(const void* p) {
    uint32_t a;
    asm("{ .reg .u64 t; cvta.to.shared.u64 t, %1; cvt.u32.u64 %0, t; }"
        : "=r"(a) : "l"(p));
    return a;
}
__device__ __forceinline__ float f2tf32(float f) {   // round-to-nearest tf32
    uint32_t o;
    asm("cvt.rna.tf32.f32 %0, %1;" : "=r"(o) : "f"(f));
    return __uint_as_float(o);
}
#define CP_ASYNC16(dst, src) \
    asm volatile("cp.async.cg.shared.global [%0], [%1], 16;" \
                 :: "r"(dst), "l"(src) : "memory")
#define CP_COMMIT() asm volatile("cp.async.commit_group;" ::: "memory")
#define CP_WAIT1()  asm volatile("cp.async.wait_group 1;" ::: "memory")
__device__ __forceinline__ uint32_t LDS(uint32_t a) {
    uint32_t v;
    asm volatile("ld.shared.b32 %0, [%1];" : "=r"(v) : "r"(a));
    return v;
}
#define MMA_TF32(d, a, b) \
    asm volatile("mma.sync.aligned.m16n8k8.row.col.f32.tf32.tf32.f32 " \
        "{%0,%1,%2,%3}, {%4,%5,%6,%7}, {%8,%9}, {%0,%1,%2,%3};" \
        : "+f"((d)[0]), "+f"((d)[1]), "+f"((d)[2]), "+f"((d)[3]) \
        : "r"((a)[0]), "r"((a)[1]), "r"((a)[2]), "r"((a)[3]), \
          "r"((b)[0]), "r"((b)[1]))

// ---------------- 3-NN per query point ---------------------------------------
__global__ void knn_kernel(const float* __restrict__ xyz1,
                           const float* __restrict__ xyz2) {
    __shared__ float4 sp[Sp];
    const int b = blockIdx.x >> 5;
    const int n = ((blockIdx.x & 31) << 8) + threadIdx.x;
    const float* x2 = xyz2 + (size_t)b * Sp * 3;
    for (int s = threadIdx.x; s < Sp; s += 256) {
        float px = x2[3 * s], py = x2[3 * s + 1], pz = x2[3 * s + 2];
        sp[s] = make_float4(px, py, pz, px * px + py * py + pz * pz);
    }
    __syncthreads();
    const float* q = xyz1 + ((size_t)b * Np + n) * 3;
    const float qx = q[0], qy = q[1], qz = q[2];
    const float q2 = qx * qx + qy * qy + qz * qz;
    float e0 = 3.4e38f, e1 = 3.4e38f, e2v = 3.4e38f;
    int i0 = 0, i1 = 0, i2 = 0;
#pragma unroll 4
    for (int s = 0; s < Sp; s++) {
        float4 p = sp[s];
        float dot = fmaf(qx, p.x, fmaf(qy, p.y, qz * p.z));
        float d2 = (q2 + p.w) - 2.0f * dot;      // same formula as reference
        if (d2 < e2v) {
            if (d2 < e1) {
                e2v = e1; i2 = i1;
                if (d2 < e0) { e1 = e0; i1 = i0; e0 = d2; i0 = s; }
                else         { e1 = d2; i1 = s; }
            } else { e2v = d2; i2 = s; }
        }
    }
    float d0 = sqrtf(fmaxf(e0,  0.f)) + 1e-10f;
    float d1 = sqrtf(fmaxf(e1,  0.f)) + 1e-10f;
    float d2 = sqrtf(fmaxf(e2v, 0.f)) + 1e-10f;
    float w0 = 1.f / d0, w1 = 1.f / d1, w2 = 1.f / d2;
    float inv = 1.f / (w0 + w1 + w2);
    const int m = b * Np + n;
    g_idx[3 * m] = i0; g_idx[3 * m + 1] = i1; g_idx[3 * m + 2] = i2;
    g_wt [3 * m] = w0 * inv; g_wt[3 * m + 1] = w1 * inv; g_wt[3 * m + 2] = w2 * inv;
}

// ---------------- interpolate + concat => x [M x 384] (tf32-rounded) ---------
__global__ void build_x_kernel(const float* __restrict__ f1,
                               const float* __restrict__ f2) {
    const int m = blockIdx.x;
    const int b = m >> 13;
    const int t = threadIdx.x;
    const int i0 = g_idx[3 * m], i1 = g_idx[3 * m + 1], i2 = g_idx[3 * m + 2];
    const float w0 = g_wt[3 * m], w1 = g_wt[3 * m + 1], w2 = g_wt[3 * m + 2];
    const float* r0 = f2 + ((size_t)b * Sp + i0) * C2;
    const float* r1 = f2 + ((size_t)b * Sp + i1) * C2;
    const float* r2 = f2 + ((size_t)b * Sp + i2) * C2;
    float* xr = g_x + (size_t)m * CIN;
    xr[t]       = f2tf32(w0 * r0[t]       + w1 * r1[t]       + w2 * r2[t]);
    xr[t + 128] = f2tf32(w0 * r0[t + 128] + w1 * r1[t + 128] + w2 * r2[t + 128]);
    xr[C2 + t]  = f2tf32(f1[(size_t)m * C1 + t]);
}

// ---------------- weight rounding to tf32 ------------------------------------
__global__ void round_w_kernel(const float* __restrict__ W1,
                               const float* __restrict__ W2) {
    int i = blockIdx.x * 256 + threadIdx.x;
    if (i < H1 * CIN) g_w1r[i] = f2tf32(W1[i]);
    if (i < H2 * H1)  g_w2r[i] = f2tf32(W2[i]);
}

// ---------------- tf32 mma.sync GEMM -----------------------------------------
// C[M x N] = A[M x KTOT] * Bw^T, Bw row-major [N x KTOT] (both K-major, tf32).
// 128x128 CTA tile, BK=16, 8 warps (4x2), warp tile 32x64 (2x8 m16n8k8).
// 3-stage cp.async pipeline; smem rows padded to 20 floats (conflict-free lds).
template <int KTOT>
__global__ void __launch_bounds__(256)
mma_gemm_kernel(const float* __restrict__ A, const float* __restrict__ Bw,
                float* __restrict__ C, int N) {
    constexpr int NITER = KTOT / 16;
    constexpr int LDP = 20;                      // padded row stride (floats)
    constexpr int STG_FLOATS = 2 * 128 * LDP;    // A + B per stage = 5120
    extern __shared__ float sm[];
    const int tid = threadIdx.x;
    const int lane = tid & 31;
    const int g = lane >> 2, t = lane & 3;
    const int wid = tid >> 5;
    const int wm = wid & 3, wn = wid >> 2;
    const int m0 = blockIdx.x << 7;
    const int n0 = blockIdx.y << 7;
    const uint32_t sbase = smem_u32(sm);

    const float* Ag = A  + (size_t)m0 * KTOT;
    const float* Bg = Bw + (size_t)n0 * KTOT;

    auto issue = [&](int s, int kc) {
        uint32_t st = sbase + (uint32_t)s * STG_FLOATS * 4;
#pragma unroll
        for (int h = 0; h < 2; h++) {
            int c = h * 256 + tid;               // 0..511
            int row = c >> 2, ko = (c & 3) * 4;
            CP_ASYNC16(st + (row * LDP + ko) * 4,
                       Ag + (size_t)row * KTOT + kc * 16 + ko);
        }
        uint32_t stb = st + 128 * LDP * 4;
#pragma unroll
        for (int h = 0; h < 2; h++) {
            int c = h * 256 + tid;
            int row = c >> 2, ko = (c & 3) * 4;
            CP_ASYNC16(stb + (row * LDP + ko) * 4,
                       Bg + (size_t)row * KTOT + kc * 16 + ko);
        }
    };

    issue(0, 0); CP_COMMIT();
    issue(1, 1); CP_COMMIT();

    float acc[2][8][4];
#pragma unroll
    for (int mt = 0; mt < 2; mt++)
#pragma unroll
        for (int nt = 0; nt < 8; nt++)
#pragma unroll
            for (int j = 0; j < 4; j++) acc[mt][nt][j] = 0.f;

    for (int it = 0; it < NITER; ++it) {
        CP_WAIT1();
        __syncthreads();
        const int nk = it + 2;
        if (nk < NITER) issue(nk % 3, nk);
        CP_COMMIT();
        const uint32_t st = sbase + (uint32_t)(it % 3) * STG_FLOATS * 4;
        const uint32_t aB = st, bB = st + 128 * LDP * 4;
#pragma unroll
        for (int ks = 0; ks < 2; ks++) {
            const int kk = ks * 8;
            uint32_t a[2][4], b[8][2];
#pragma unroll
            for (int mt = 0; mt < 2; mt++) {
                uint32_t p = aB + (((wm * 32 + mt * 16 + g) * LDP) + kk + t) * 4;
                a[mt][0] = LDS(p);
                a[mt][1] = LDS(p + 8 * LDP * 4);
                a[mt][2] = LDS(p + 16);
                a[mt][3] = LDS(p + 8 * LDP * 4 + 16);
            }
#pragma unroll
            for (int nt = 0; nt < 8; nt++) {
                uint32_t p = bB + (((wn * 64 + nt * 8 + g) * LDP) + kk + t) * 4;
                b[nt][0] = LDS(p);
                b[nt][1] = LDS(p + 16);
            }
#pragma unroll
            for (int mt = 0; mt < 2; mt++)
#pragma unroll
                for (int nt = 0; nt < 8; nt++)
                    MMA_TF32(acc[mt][nt], a[mt], b[nt]);
        }
    }
    // epilogue
#pragma unroll
    for (int mt = 0; mt < 2; mt++) {
        int r0 = m0 + wm * 32 + mt * 16 + g;
#pragma unroll
        for (int nt = 0; nt < 8; nt++) {
            int c0 = n0 + wn * 64 + nt * 8 + t * 2;
            *(float2*)&C[(size_t)r0 * N + c0] =
                make_float2(acc[mt][nt][0], acc[mt][nt][1]);
            *(float2*)&C[(size_t)(r0 + 8) * N + c0] =
                make_float2(acc[mt][nt][2], acc[mt][nt][3]);
        }
    }
}

// ---------------- BN stats: deterministic two-level reduction ----------------
template <int C>
__global__ void stats_partial_kernel(const float* __restrict__ Y) {
    const int c = threadIdx.x;
    constexpr int RPB = M / 256;
    size_t base = (size_t)blockIdx.x * RPB * C + c;
    float s = 0.f, s2 = 0.f;
    for (int r = 0; r < RPB; r++) {
        float v = Y[base + (size_t)r * C];
        s += v; s2 = fmaf(v, v, s2);
    }
    g_psum[blockIdx.x * C + c] = s;
    g_psq [blockIdx.x * C + c] = s2;
}

template <int C>
__global__ void stats_final_kernel(const float* __restrict__ g,
                                   const float* __restrict__ be,
                                   float* __restrict__ scale,
                                   float* __restrict__ shift) {
    const int c = threadIdx.x;
    float s = 0.f, s2 = 0.f;
    for (int r = 0; r < 256; r++) { s += g_psum[r * C + c]; s2 += g_psq[r * C + c]; }
    const float invM = 1.0f / (float)M;
    float mean = s * invM;
    float var  = fmaf(s2, invM, -mean * mean);
    float sc   = g[c] * rsqrtf(var + 1e-5f);
    scale[c] = sc;
    shift[c] = fmaf(-mean, sc, be[c]);     // conv bias cancels in training BN
}

// ---------------- BN1 + ReLU + tf32 round, in place on y1 --------------------
__global__ void bn1_apply_kernel(float* __restrict__ y) {
    int i = blockIdx.x * 256 + threadIdx.x;   // float4 index
    float4 v = ((float4*)y)[i];
    int c = (i << 2) & (H1 - 1);
    v.x = f2tf32(fmaxf(fmaf(v.x, g_scale1[c],     g_shift1[c]),     0.f));
    v.y = f2tf32(fmaxf(fmaf(v.y, g_scale1[c + 1], g_shift1[c + 1]), 0.f));
    v.z = f2tf32(fmaxf(fmaf(v.z, g_scale1[c + 2], g_shift1[c + 2]), 0.f));
    v.w = f2tf32(fmaxf(fmaf(v.w, g_scale1[c + 3], g_shift1[c + 3]), 0.f));
    ((float4*)y)[i] = v;
}

// ---------------- final BN+ReLU in place on d_out ----------------------------
__global__ void bnrelu_out_kernel(float* __restrict__ out) {
    int i = blockIdx.x * blockDim.x + threadIdx.x;
    float4 v = ((float4*)out)[i];
    int c = (i << 2) & (H2 - 1);
    v.x = fmaxf(fmaf(v.x, g_scale2[c],     g_shift2[c]),     0.f);
    v.y = fmaxf(fmaf(v.y, g_scale2[c + 1], g_shift2[c + 1]), 0.f);
    v.z = fmaxf(fmaf(v.z, g_scale2[c + 2], g_shift2[c + 2]), 0.f);
    v.w = fmaxf(fmaf(v.w, g_scale2[c + 3], g_shift2[c + 3]), 0.f);
    ((float4*)out)[i] = v;
}

// ---------------- launch ------------------------------------------------------
extern "C" void kernel_launch(void* const* d_in, const int* in_sizes, int n_in,
                              void* d_out, int out_size) {
    const float* xyz1 = (const float*)d_in[0];
    const float* xyz2 = (const float*)d_in[1];
    const float* f1   = (const float*)d_in[2];
    const float* f2   = (const float*)d_in[3];
    const float* W1   = (const float*)d_in[4];
    const float* g1   = (const float*)d_in[6];
    const float* be1  = (const float*)d_in[7];
    const float* W2   = (const float*)d_in[8];
    const float* g2   = (const float*)d_in[10];
    const float* be2  = (const float*)d_in[11];
    float* out = (float*)d_out;

    float *px, *py1, *pw1, *pw2, *ps1, *pt1, *ps2, *pt2;
    cudaGetSymbolAddress((void**)&px,  g_x);
    cudaGetSymbolAddress((void**)&py1, g_y1);
    cudaGetSymbolAddress((void**)&pw1, g_w1r);
    cudaGetSymbolAddress((void**)&pw2, g_w2r);
    cudaGetSymbolAddress((void**)&ps1, g_scale1);
    cudaGetSymbolAddress((void**)&pt1, g_shift1);
    cudaGetSymbolAddress((void**)&ps2, g_scale2);
    cudaGetSymbolAddress((void**)&pt2, g_shift2);

    constexpr int SMEM = 3 * 2 * 128 * 20 * 4;   // 61440 bytes
    cudaFuncSetAttribute(mma_gemm_kernel<CIN>,
                         cudaFuncAttributeMaxDynamicSharedMemorySize, SMEM);
    cudaFuncSetAttribute(mma_gemm_kernel<H1>,
                         cudaFuncAttributeMaxDynamicSharedMemorySize, SMEM);

    round_w_kernel<<<(H1 * CIN + 255) / 256, 256>>>(W1, W2);
    knn_kernel<<<Bsz * 32, 256>>>(xyz1, xyz2);
    build_x_kernel<<<M, 128>>>(f1, f2);

    // layer 1: y1 = x @ W1^T  (bias cancels in training-mode BN)
    mma_gemm_kernel<CIN><<<dim3(M / 128, H1 / 128), 256, SMEM>>>(px, pw1, py1, H1);
    stats_partial_kernel<H1><<<256, H1>>>(py1);
    stats_final_kernel<H1><<<1, H1>>>(g1, be1, ps1, pt1);
    bn1_apply_kernel<<<(M * H1 / 4) / 256, 256>>>(py1);

    // layer 2: y2 = bn1(y1) @ W2^T
    mma_gemm_kernel<H1><<<dim3(M / 128, H2 / 128), 256, SMEM>>>(py1, pw2, out, H2);
    stats_partial_kernel<H2><<<256, H2>>>(out);
    stats_final_kernel<H2><<<1, H2>>>(g2, be2, ps2, pt2);

    bnrelu_out_kernel<<<(M * H2 / 4) / 256, 256>>>(out);
}